// round 17
// baseline (speedup 1.0000x reference)
#include <cuda_runtime.h>
#include <cuda_fp16.h>
#include <cstddef>

#define BB 2
#define TT 2048
#define DD 1024
#define HH 16
#define HD 64
#define TD3 (3*DD)

// Scratch (device globals: allowed; cudaMalloc is not)
__device__ __half g_Xh[(size_t)BB*TT*DD];         // X fp16
__device__ __half g_WhKQV[(size_t)TD3*DD];        // W_KQV^T [3D][D] fp16
__device__ __half g_WhOut[(size_t)DD*DD];         // W_out^T [D][D] fp16
__device__ __half g_resh[(size_t)BB*TT*TD3];      // QKV projection fp16
__device__ __half g_ctxh[(size_t)BB*TT*DD];       // context fp16
__device__ float  g_inv[(size_t)BB*HH*TT];        // per-row 1/softmax-sum
__device__ float  g_attn[(size_t)BB*HH*TT*TT];    // attn fallback

// ---------------------------------------------------------------------------
// helpers
// ---------------------------------------------------------------------------
__device__ __forceinline__ void mma_f16(float* c, const unsigned* a, const unsigned* b) {
    asm volatile("mma.sync.aligned.m16n8k16.row.col.f32.f16.f16.f32 "
        "{%0,%1,%2,%3}, {%4,%5,%6,%7}, {%8,%9}, {%0,%1,%2,%3};"
        : "+f"(c[0]), "+f"(c[1]), "+f"(c[2]), "+f"(c[3])
        : "r"(a[0]), "r"(a[1]), "r"(a[2]), "r"(a[3]), "r"(b[0]), "r"(b[1]));
}
__device__ __forceinline__ unsigned smem_u32(const void* p) {
    return (unsigned)__cvta_generic_to_shared(p);
}
__device__ __forceinline__ void cp16(unsigned dst, const void* src) {
    asm volatile("cp.async.cg.shared.global [%0], [%1], 16;" :: "r"(dst), "l"(src));
}
#define CP_COMMIT() asm volatile("cp.async.commit_group;" ::: "memory")
#define CP_WAIT1()  asm volatile("cp.async.wait_group 1;" ::: "memory")
#define CP_WAIT0()  asm volatile("cp.async.wait_group 0;" ::: "memory")

__device__ __forceinline__ void ldsm_x4(unsigned* r, unsigned addr) {
    asm volatile("ldmatrix.sync.aligned.m8n8.x4.shared.b16 {%0,%1,%2,%3}, [%4];"
        : "=r"(r[0]), "=r"(r[1]), "=r"(r[2]), "=r"(r[3]) : "r"(addr));
}
__device__ __forceinline__ void ldsm_x4t(unsigned* r, unsigned addr) {
    asm volatile("ldmatrix.sync.aligned.m8n8.x4.trans.shared.b16 {%0,%1,%2,%3}, [%4];"
        : "=r"(r[0]), "=r"(r[1]), "=r"(r[2]), "=r"(r[3]) : "r"(addr));
}
// streaming stores (write-once data; keep it out of L2's hot set)
__device__ __forceinline__ void stg_cs2(float* p, float2 v) {
    asm volatile("st.global.cs.v2.f32 [%0], {%1,%2};" :: "l"(p), "f"(v.x), "f"(v.y) : "memory");
}
__device__ __forceinline__ void stg_cs4(float* p, float4 v) {
    asm volatile("st.global.cs.v4.f32 [%0], {%1,%2,%3,%4};"
        :: "l"(p), "f"(v.x), "f"(v.y), "f"(v.z), "f"(v.w) : "memory");
}

// ---------------------------------------------------------------------------
// prep kernels
// ---------------------------------------------------------------------------
__global__ __launch_bounds__(256) void to_half(
    const float* __restrict__ in, __half* __restrict__ out, int n4)
{
    int i = blockIdx.x * 256 + threadIdx.x;
    int stride = gridDim.x * 256;
    for (; i < n4; i += stride) {
        float4 v = *(const float4*)(in + (size_t)i * 4);
        __half2 h0 = __floats2half2_rn(v.x, v.y);
        __half2 h1 = __floats2half2_rn(v.z, v.w);
        ((__half2*)out)[(size_t)i * 2]     = h0;
        ((__half2*)out)[(size_t)i * 2 + 1] = h1;
    }
}

// in[R][C] float -> out[C][R] fp16
__global__ __launch_bounds__(256) void transpose_half(
    const float* __restrict__ in, __half* __restrict__ out, int R, int C)
{
    __shared__ float t[32][33];
    int bx = blockIdx.x * 32;   // C
    int by = blockIdx.y * 32;   // R
    int tx = threadIdx.x & 31, ty = threadIdx.x >> 5;
    #pragma unroll
    for (int i = 0; i < 4; i++)
        t[ty + i*8][tx] = in[(size_t)(by + ty + i*8) * C + bx + tx];
    __syncthreads();
    #pragma unroll
    for (int i = 0; i < 4; i++)
        out[(size_t)(bx + ty + i*8) * R + by + tx] = __float2half_rn(t[tx][ty + i*8]);
}

// ---------------------------------------------------------------------------
// NT fp16 GEMM: C[M,N] = A[M,K] @ Bt[N,K]^T, fp16 operands, fp32 accum.
// block 128x128, k-chunk 64, 3-stage cp.async, all fragments via ldmatrix.
// ---------------------------------------------------------------------------
#define GH_STRIDE 72
#define GH_SZ (128*GH_STRIDE)                 // halfs per stage per matrix
#define GEMM_SMEM (3*2*GH_SZ*2)               // 110,592 B

__global__ __launch_bounds__(256, 2) void gemm_f16_nt(
    const __half* __restrict__ A, const __half* __restrict__ Bt,
    void* __restrict__ Cv, int M, int N, int K, int out_half)
{
    extern __shared__ __half gsh[];
    __half* As = gsh;                // [3][128][72]
    __half* Bs = gsh + 3*GH_SZ;      // [3][128][72]

    int tid = threadIdx.x;
    int lane = tid & 31, wid = tid >> 5;
    int wm = (wid >> 2) * 64;
    int wn = (wid & 3) * 32;
    int g  = lane >> 2, tg = lane & 3;

    size_t by = (size_t)blockIdx.y * 128;
    size_t bx = (size_t)blockIdx.x * 128;

    int r = tid >> 1, j = tid & 1;
    const __half* Ab = A  + (by + r) * K;
    const __half* Bb = Bt + (bx + r) * K;

    int mat = lane >> 3, rowin = lane & 7;
    unsigned a_off[4], b_off[2];
    #pragma unroll
    for (int mt = 0; mt < 4; mt++)
        a_off[mt] = (unsigned)(((wm + mt*16 + (mat & 1)*8 + rowin) * GH_STRIDE
                                + (mat >> 1) * 8) * 2);
    #pragma unroll
    for (int ntp = 0; ntp < 2; ntp++)
        b_off[ntp] = (unsigned)(((wn + ntp*16 + (mat >> 1)*8 + rowin) * GH_STRIDE
                                 + (mat & 1) * 8) * 2);
    unsigned asb = smem_u32(As);
    unsigned bsb = smem_u32(Bs);

    float acc[4][4][4];
    #pragma unroll
    for (int i = 0; i < 4; i++)
        #pragma unroll
        for (int jj = 0; jj < 4; jj++)
            #pragma unroll
            for (int f = 0; f < 4; f++) acc[i][jj][f] = 0.f;

    auto load_stage = [&](int s, int k0) {
        unsigned ad = smem_u32(&As[s*GH_SZ + r*GH_STRIDE]);
        unsigned bd = smem_u32(&Bs[s*GH_SZ + r*GH_STRIDE]);
        const __half* asrc = Ab + k0;
        const __half* bsrc = Bb + k0;
        #pragma unroll
        for (int i = 0; i < 4; i++) {
            int c4 = j * 4 + i;
            cp16(ad + c4*16, asrc + c4*8);
            cp16(bd + c4*16, bsrc + c4*8);
        }
    };

    const int NIT = K >> 6;
    load_stage(0, 0);  CP_COMMIT();
    load_stage(1, 64); CP_COMMIT();

    #pragma unroll 1
    for (int it = 0; it < NIT; it++) {
        CP_WAIT1();
        __syncthreads();
        if (it + 2 < NIT) load_stage((it + 2) % 3, (it + 2) << 6);
        CP_COMMIT();

        unsigned abase = asb + (unsigned)((it % 3) * GH_SZ * 2);
        unsigned bbase = bsb + (unsigned)((it % 3) * GH_SZ * 2);
        #pragma unroll
        for (int ks = 0; ks < 4; ks++) {
            unsigned kb2 = (unsigned)(ks * 32);
            unsigned a[4][4], bq[2][4];
            #pragma unroll
            for (int mt = 0; mt < 4; mt++)
                ldsm_x4(a[mt], abase + a_off[mt] + kb2);
            #pragma unroll
            for (int ntp = 0; ntp < 2; ntp++)
                ldsm_x4(bq[ntp], bbase + b_off[ntp] + kb2);
            #pragma unroll
            for (int mt = 0; mt < 4; mt++)
                #pragma unroll
                for (int nt = 0; nt < 4; nt++)
                    mma_f16(acc[mt][nt], a[mt], &bq[nt >> 1][(nt & 1) * 2]);
        }
    }

    #pragma unroll
    for (int mt = 0; mt < 4; mt++) {
        #pragma unroll
        for (int nt = 0; nt < 4; nt++) {
            size_t rr = by + wm + mt * 16 + g;
            size_t cc = bx + wn + nt * 8 + tg * 2;
            if (out_half) {
                __half* C = (__half*)Cv;
                *(__half2*)(C + rr * N + cc) =
                    __floats2half2_rn(acc[mt][nt][0], acc[mt][nt][1]);
                *(__half2*)(C + (rr + 8) * N + cc) =
                    __floats2half2_rn(acc[mt][nt][2], acc[mt][nt][3]);
            } else {
                float* C = (float*)Cv;
                *(float2*)(C + rr * N + cc)       = make_float2(acc[mt][nt][0], acc[mt][nt][1]);
                *(float2*)(C + (rr + 8) * N + cc) = make_float2(acc[mt][nt][2], acc[mt][nt][3]);
            }
        }
    }
}

// ---------------------------------------------------------------------------
// attn_fused (pass 1): scores mma -> exp -> Es -> ctx mma; rowsums -> inv.
// 2 CTAs/SM (111 KB smem each). Exports inv; writes ctx fp16.
// ---------------------------------------------------------------------------
#define TS 72                       // K/Q/V tile stride (halfs)
#define ES_STRIDE 136
#define H_KS 0
#define H_ES 9216
#define H_Q0 26624
#define H_Q1 35840
#define H_V  45056
#define H_END 54272                 // halfs
#define B_RP (H_END*2)              // bytes: rp floats
#define B_INV (B_RP + 2048)
#define ATTN_SMEM (B_INV + 512 + 64)   // 111,168 B -> 2 CTAs/SM

__global__ __launch_bounds__(256, 2) void attn_fused(
    const __half* __restrict__ res, __half* __restrict__ ctx,
    float* __restrict__ inv_g)
{
    extern __shared__ __half ash[];
    __half* Ks  = ash + H_KS;
    __half* Es  = ash + H_ES;
    __half* Qb0 = ash + H_Q0;
    __half* Qb1 = ash + H_Q1;
    __half* Vs  = ash + H_V;
    float* rp    = (float*)((char*)ash + B_RP);
    float* inv_s = (float*)((char*)ash + B_INV);

    int kb = (TT/128 - 1) - blockIdx.x;
    int bh = blockIdx.y;
    int b = bh / HH, h = bh % HH;
    int tid = threadIdx.x;
    int lane = tid & 31, wid = tid >> 5;
    int wm = (wid >> 2) * 64, wn = (wid & 3) * 32;
    int wm2 = (wid >> 1) * 32, wn2 = (wid & 1) * 32;
    int g = lane >> 2, tg = lane & 3;

    const __half* Kg = res + (size_t)b * TT * TD3 + (size_t)h * HD;
    const __half* Qg = res + (size_t)b * TT * TD3 + DD + (size_t)h * HD;
    const __half* Vg = res + (size_t)b * TT * TD3 + 2 * DD + (size_t)h * HD;

    int qr = tid >> 1, qj = tid & 1;

    int mat = lane >> 3, rowin = lane & 7;
    unsigned ks_off[4], es_off[2], q_off[2], v_off[2];
    #pragma unroll
    for (int mt = 0; mt < 4; mt++)
        ks_off[mt] = (unsigned)(((wm + mt*16 + (mat & 1)*8 + rowin) * TS
                                 + (mat >> 1) * 8) * 2);
    #pragma unroll
    for (int mt = 0; mt < 2; mt++)
        es_off[mt] = (unsigned)(((wm2 + mt*16 + (mat & 1)*8 + rowin) * ES_STRIDE
                                 + (mat >> 1) * 8) * 2);
    #pragma unroll
    for (int ntp = 0; ntp < 2; ntp++) {
        q_off[ntp] = (unsigned)(((wn + ntp*16 + (mat >> 1)*8 + rowin) * TS
                                 + (mat & 1) * 8) * 2);
        v_off[ntp] = (unsigned)((((mat & 1)*8 + rowin) * TS
                                 + wn2 + ntp*16 + (mat >> 1)*8) * 2);
    }
    unsigned ksb = smem_u32(Ks);
    unsigned esb = smem_u32(Es);
    unsigned q0b = smem_u32(Qb0);
    unsigned q1b = smem_u32(Qb1);
    unsigned vsb = smem_u32(Vs);

    auto loadK = [&]() {
        unsigned base = smem_u32(&Ks[qr * TS]);
        const __half* src = Kg + (size_t)(kb * 128 + qr) * TD3;
        #pragma unroll
        for (int i = 0; i < 4; i++) {
            int c4 = qj * 4 + i;
            cp16(base + c4*16, src + c4*8);
        }
    };
    auto loadQ = [&](__half* buf, int qb) {
        unsigned base = smem_u32(&buf[qr * TS]);
        const __half* src = Qg + (size_t)(qb * 128 + qr) * TD3;
        #pragma unroll
        for (int i = 0; i < 4; i++) {
            int c4 = qj * 4 + i;
            cp16(base + c4*16, src + c4*8);
        }
    };
    auto loadV = [&](int qb) {
        unsigned base = smem_u32(&Vs[qr * TS]);
        const __half* src = Vg + (size_t)(qb * 128 + qr) * TD3;
        #pragma unroll
        for (int i = 0; i < 4; i++) {
            int c4 = qj * 4 + i;
            cp16(base + c4*16, src + c4*8);
        }
    };

    float rs0[4] = {0.f,0.f,0.f,0.f}, rs1[4] = {0.f,0.f,0.f,0.f};
    float acc2[2][4][4];
    #pragma unroll
    for (int i = 0; i < 2; i++)
        #pragma unroll
        for (int jj = 0; jj < 4; jj++)
            #pragma unroll
            for (int f = 0; f < 4; f++) acc2[i][jj][f] = 0.f;

    const float scale = 0.125f;

    loadK(); loadQ(Qb0, 0); CP_COMMIT();
    #pragma unroll 1
    for (int qb = 0; qb <= kb; qb++) {
        unsigned qcb = (qb & 1) ? q1b : q0b;
        __half* Qnxt = (qb & 1) ? Qb0 : Qb1;
        loadV(qb); CP_COMMIT();
        CP_WAIT1();
        __syncthreads();

        float acc[4][4][4];
        #pragma unroll
        for (int i = 0; i < 4; i++)
            #pragma unroll
            for (int jj = 0; jj < 4; jj++)
                #pragma unroll
                for (int f = 0; f < 4; f++) acc[i][jj][f] = 0.f;

        #pragma unroll
        for (int ks = 0; ks < 4; ks++) {
            unsigned kb2 = (unsigned)(ks * 32);
            unsigned a[4][4], bq[2][4];
            #pragma unroll
            for (int mt = 0; mt < 4; mt++)
                ldsm_x4(a[mt], ksb + ks_off[mt] + kb2);
            #pragma unroll
            for (int ntp = 0; ntp < 2; ntp++)
                ldsm_x4(bq[ntp], qcb + q_off[ntp] + kb2);
            #pragma unroll
            for (int mt = 0; mt < 4; mt++)
                #pragma unroll
                for (int nt = 0; nt < 4; nt++)
                    mma_f16(acc[mt][nt], a[mt], &bq[nt >> 1][(nt & 1) * 2]);
        }

        if (qb < kb) loadQ(Qnxt, qb + 1);
        CP_COMMIT();

        bool diag = (qb == kb);
        #pragma unroll
        for (int mt = 0; mt < 4; mt++) {
            #pragma unroll
            for (int nt = 0; nt < 4; nt++) {
                int r = wm + mt * 16 + g;
                int c = wn + nt * 8 + tg * 2;
                int rg0 = kb * 128 + r, rg1 = rg0 + 8;
                int cg  = qb * 128 + c;
                float e0 = (diag && cg     > rg0) ? 0.f : __expf(acc[mt][nt][0] * scale);
                float e1 = (diag && cg + 1 > rg0) ? 0.f : __expf(acc[mt][nt][1] * scale);
                float e2 = (diag && cg     > rg1) ? 0.f : __expf(acc[mt][nt][2] * scale);
                float e3 = (diag && cg + 1 > rg1) ? 0.f : __expf(acc[mt][nt][3] * scale);
                rs0[mt] += e0 + e1;
                rs1[mt] += e2 + e3;
                *(__half2*)&Es[r*ES_STRIDE + c]     = __floats2half2_rn(e0, e1);
                *(__half2*)&Es[(r+8)*ES_STRIDE + c] = __floats2half2_rn(e2, e3);
            }
        }
        CP_WAIT1();
        __syncthreads();

        // ctx mma: acc2 += Es[128 x 128] @ V[128 x 64]
        #pragma unroll
        for (int ks = 0; ks < 8; ks++) {
            unsigned a2[2][4], bv[2][4];
            #pragma unroll
            for (int mt = 0; mt < 2; mt++)
                ldsm_x4(a2[mt], esb + es_off[mt] + (unsigned)(ks * 32));
            #pragma unroll
            for (int ntp = 0; ntp < 2; ntp++)
                ldsm_x4t(bv[ntp], vsb + v_off[ntp] + (unsigned)(ks * 16 * TS * 2));
            #pragma unroll
            for (int mt = 0; mt < 2; mt++)
                #pragma unroll
                for (int nt = 0; nt < 4; nt++)
                    mma_f16(acc2[mt][nt], a2[mt], &bv[nt >> 1][(nt & 1) * 2]);
        }
        __syncthreads();
    }

    // rowsum reduce -> inv (smem + export)
    #pragma unroll
    for (int mt = 0; mt < 4; mt++) {
        float s0 = rs0[mt], s1 = rs1[mt];
        s0 += __shfl_xor_sync(0xffffffffu, s0, 1);
        s0 += __shfl_xor_sync(0xffffffffu, s0, 2);
        s1 += __shfl_xor_sync(0xffffffffu, s1, 1);
        s1 += __shfl_xor_sync(0xffffffffu, s1, 2);
        if (tg == 0) {
            rp[(wm + mt*16 + g)*4 + (wid & 3)]     = s0;
            rp[(wm + mt*16 + g + 8)*4 + (wid & 3)] = s1;
        }
    }
    __syncthreads();
    if (tid < 128) {
        float iv = 1.f / (rp[tid*4] + rp[tid*4+1] + rp[tid*4+2] + rp[tid*4+3]);
        inv_s[tid] = iv;
        inv_g[(size_t)bh * TT + kb * 128 + tid] = iv;
    }
    __syncthreads();

    // scale ctx, write fp16 (consumed by out-GEMM)
    {
        __half* Cg = ctx + (size_t)b * TT * DD + (size_t)h * HD;
        #pragma unroll
        for (int mt = 0; mt < 2; mt++) {
            int r2 = wm2 + mt * 16 + g;
            float il = inv_s[r2], ih = inv_s[r2 + 8];
            #pragma unroll
            for (int nt = 0; nt < 4; nt++) {
                size_t rA = (size_t)kb * 128 + r2;
                int c = wn2 + nt * 8 + tg * 2;
                *(__half2*)(Cg + rA * DD + c) =
                    __floats2half2_rn(acc2[mt][nt][0] * il, acc2[mt][nt][1] * il);
                *(__half2*)(Cg + (rA + 8) * DD + c) =
                    __floats2half2_rn(acc2[mt][nt][2] * ih, acc2[mt][nt][3] * ih);
            }
        }
    }
}

// ---------------------------------------------------------------------------
// attn_write: one 128x128 tile per CTA, fp16 score recompute (bit-identical
// to pass 1), exp*inv, single streaming attn write. Zero tiles early-exit.
// ---------------------------------------------------------------------------
#define AW_SMEM (2 * 9216 * 2)   // 36,864 B

__global__ __launch_bounds__(256, 2) void attn_write(
    const __half* __restrict__ res, const float* __restrict__ inv_g,
    float* __restrict__ attn)
{
    extern __shared__ __half ash2[];
    __half* Ks = ash2;
    __half* Qs = ash2 + 9216;

    int qb = blockIdx.x, kb = blockIdx.y, bh = blockIdx.z;
    int b = bh / HH, h = bh % HH;
    int tid = threadIdx.x;
    float* out = attn + ((size_t)bh * TT + (size_t)kb * 128) * TT + (size_t)qb * 128;

    if (qb > kb) {   // fully masked -> zeros (streaming stores)
        float4 z = make_float4(0.f, 0.f, 0.f, 0.f);
        #pragma unroll
        for (int i = tid; i < 128 * 32; i += 256)
            stg_cs4(out + (size_t)(i >> 5) * TT + (i & 31) * 4, z);
        return;
    }

    int lane = tid & 31, wid = tid >> 5;
    int wm = (wid >> 2) * 64, wn = (wid & 3) * 32;
    int g = lane >> 2, tg = lane & 3;

    const __half* Kg = res + (size_t)b * TT * TD3 + (size_t)h * HD;
    const __half* Qg = res + (size_t)b * TT * TD3 + DD + (size_t)h * HD;

    int qr = tid >> 1, qj = tid & 1;
    {
        unsigned kd = smem_u32(&Ks[qr * TS]);
        unsigned qd = smem_u32(&Qs[qr * TS]);
        const __half* ksrc = Kg + (size_t)(kb * 128 + qr) * TD3;
        const __half* qsrc = Qg + (size_t)(qb * 128 + qr) * TD3;
        #pragma unroll
        for (int i = 0; i < 4; i++) {
            int c4 = qj * 4 + i;
            cp16(kd + c4*16, ksrc + c4*8);
            cp16(qd + c4*16, qsrc + c4*8);
        }
    }
    CP_COMMIT();

    int mat = lane >> 3, rowin = lane & 7;
    unsigned ks_off[4], q_off[2];
    #pragma unroll
    for (int mt = 0; mt < 4; mt++)
        ks_off[mt] = (unsigned)(((wm + mt*16 + (mat & 1)*8 + rowin) * TS
                                 + (mat >> 1) * 8) * 2);
    #pragma unroll
    for (int ntp = 0; ntp < 2; ntp++)
        q_off[ntp] = (unsigned)(((wn + ntp*16 + (mat >> 1)*8 + rowin) * TS
                                 + (mat & 1) * 8) * 2);
    unsigned ksb = smem_u32(Ks);
    unsigned qsb = smem_u32(Qs);

    float iv0[4], iv1[4];
    #pragma unroll
    for (int mt = 0; mt < 4; mt++) {
        iv0[mt] = inv_g[(size_t)bh * TT + kb * 128 + wm + mt*16 + g];
        iv1[mt] = inv_g[(size_t)bh * TT + kb * 128 + wm + mt*16 + g + 8];
    }

    CP_WAIT0();
    __syncthreads();

    float acc[4][4][4];
    #pragma unroll
    for (int i = 0; i < 4; i++)
        #pragma unroll
        for (int jj = 0; jj < 4; jj++)
            #pragma unroll
            for (int f = 0; f < 4; f++) acc[i][jj][f] = 0.f;

    #pragma unroll
    for (int ks = 0; ks < 4; ks++) {
        unsigned kb2 = (unsigned)(ks * 32);
        unsigned a[4][4], bq[2][4];
        #pragma unroll
        for (int mt = 0; mt < 4; mt++)
            ldsm_x4(a[mt], ksb + ks_off[mt] + kb2);
        #pragma unroll
        for (int ntp = 0; ntp < 2; ntp++)
            ldsm_x4(bq[ntp], qsb + q_off[ntp] + kb2);
        #pragma unroll
        for (int mt = 0; mt < 4; mt++)
            #pragma unroll
            for (int nt = 0; nt < 4; nt++)
                mma_f16(acc[mt][nt], a[mt], &bq[nt >> 1][(nt & 1) * 2]);
    }

    const float scale = 0.125f;
    bool diag = (qb == kb);
    #pragma unroll
    for (int mt = 0; mt < 4; mt++) {
        #pragma unroll
        for (int nt = 0; nt < 4; nt++) {
            int r = wm + mt * 16 + g;
            int c = wn + nt * 8 + tg * 2;
            int rg0 = kb * 128 + r, rg1 = rg0 + 8;
            int cg  = qb * 128 + c;
            float e0 = (diag && cg     > rg0) ? 0.f : __expf(acc[mt][nt][0]*scale) * iv0[mt];
            float e1 = (diag && cg + 1 > rg0) ? 0.f : __expf(acc[mt][nt][1]*scale) * iv0[mt];
            float e2 = (diag && cg     > rg1) ? 0.f : __expf(acc[mt][nt][2]*scale) * iv1[mt];
            float e3 = (diag && cg + 1 > rg1) ? 0.f : __expf(acc[mt][nt][3]*scale) * iv1[mt];
            stg_cs2(out + (size_t)r * TT + c,       make_float2(e0, e1));
            stg_cs2(out + (size_t)(r + 8) * TT + c, make_float2(e2, e3));
        }
    }
}

// ---------------------------------------------------------------------------
extern "C" void kernel_launch(void* const* d_in, const int* in_sizes, int n_in,
                              void* d_out, int out_size)
{
    const float* X     = (const float*)d_in[0];
    const float* W_KQV = (const float*)d_in[1];
    const float* W_out = (const float*)d_in[2];

    const size_t OUT_E  = (size_t)BB * TT * DD;
    const size_t ATTN_E = (size_t)BB * HH * TT * TT;

    __half* xh_p;  cudaGetSymbolAddress((void**)&xh_p,  g_Xh);
    __half* whk_p; cudaGetSymbolAddress((void**)&whk_p, g_WhKQV);
    __half* who_p; cudaGetSymbolAddress((void**)&who_p, g_WhOut);
    __half* resh_p; cudaGetSymbolAddress((void**)&resh_p, g_resh);
    __half* ctxh_p; cudaGetSymbolAddress((void**)&ctxh_p, g_ctxh);
    float* inv_p;  cudaGetSymbolAddress((void**)&inv_p,  g_inv);
    float* attn_s; cudaGetSymbolAddress((void**)&attn_s, g_attn);

    float* out_p = nullptr;
    float* attn_p;
    size_t osz = (size_t)out_size;
    if (osz >= OUT_E + ATTN_E) {
        out_p  = (float*)d_out;
        attn_p = (float*)d_out + OUT_E;
    } else if (osz == ATTN_E) {
        attn_p = (float*)d_out;
    } else {
        out_p  = (float*)d_out;
        attn_p = attn_s;
    }

    cudaFuncSetAttribute(gemm_f16_nt,
                         cudaFuncAttributeMaxDynamicSharedMemorySize, GEMM_SMEM);
    cudaFuncSetAttribute(attn_fused,
                         cudaFuncAttributeMaxDynamicSharedMemorySize, ATTN_SMEM);
    cudaFuncSetAttribute(attn_write,
                         cudaFuncAttributeMaxDynamicSharedMemorySize, AW_SMEM);

    // 0) prep: fp16-round X; transpose+round weights to [N][K] fp16
    to_half<<<512, 256>>>(X, xh_p, (BB*TT*DD) / 4);
    {
        dim3 grid(TD3 / 32, DD / 32);
        transpose_half<<<grid, 256>>>(W_KQV, whk_p, DD, TD3);
    }
    {
        dim3 grid(DD / 32, DD / 32);
        transpose_half<<<grid, 256>>>(W_out, who_p, DD, DD);
    }

    // 1) QKV projection (fp16 out)
    {
        dim3 grid(TD3 / 128, (BB * TT) / 128);
        gemm_f16_nt<<<grid, 256, GEMM_SMEM>>>(xh_p, whk_p, resh_p, BB * TT, TD3, DD, 1);
    }
    // 2) pass 1: ctx (fp16) + inv export (2 CTAs/SM now)
    {
        dim3 grid(TT / 128, BB * HH);
        attn_fused<<<grid, 256, ATTN_SMEM>>>(resh_p, ctxh_p, inv_p);
    }
    // 3) write normalized attn (one tile per CTA, streaming stores)
    {
        dim3 grid(TT / 128, TT / 128, BB * HH);
        attn_write<<<grid, 256, AW_SMEM>>>(resh_p, inv_p, attn_p);
    }
    // 4) out = ctx @ W_out (fp32 output)
    if (out_p) {
        dim3 grid(DD / 128, (BB * TT) / 128);
        gemm_f16_nt<<<grid, 256, GEMM_SMEM>>>(ctxh_p, who_p, out_p, BB * TT, DD, DD, 0);
    }
}